// round 1
// baseline (speedup 1.0000x reference)
#include <cuda_runtime.h>
#include <math.h>

#define S_LEN 4096
#define H_DIM 2048
#define HQ 8
#define HKV 4
#define HD 256
#define WIN 1024

// ---------------- scratch (device globals; no allocation APIs) ----------------
__device__ float g_Qp[S_LEN * (HQ * HD)];    // [S, 2048] projected Q
__device__ float g_Kp[S_LEN * (HKV * HD)];   // [S, 1024]
__device__ float g_Vp[S_LEN * (HKV * HD)];   // [S, 1024]
__device__ float g_Qr[HQ * S_LEN * HD];      // [HQ][S][D] normed+roped
__device__ float g_Kr[HKV * S_LEN * HD];     // [HKV][S][D]
__device__ float g_Vr[HKV * S_LEN * HD];     // [HKV][S][D]
__device__ float g_AO[S_LEN * (HQ * HD)];    // [S, 2048] attention out

// ---------------- SGEMM: C[M,N] = A[M,K] @ B[N,K]^T (all row-major) ----------
// 128x128 block tile, BK=8, 256 threads, 8x8 micro-tile per thread.
__global__ __launch_bounds__(256, 2)
void sgemm_nt(const float* __restrict__ A, const float* __restrict__ B,
              float* __restrict__ C, int M, int N, int K) {
    __shared__ float As[8][132];   // transposed, +4 pad => conflict-free stores
    __shared__ float Bs[8][132];

    const int tid = threadIdx.x;
    const int bm = blockIdx.y * 128;
    const int bn = blockIdx.x * 128;
    const int lr = tid >> 1;            // 0..127 tile row for loading
    const int lc = (tid & 1) * 4;       // 0 or 4
    const int tx = tid & 15;
    const int ty = tid >> 4;

    const float* Ap = A + (size_t)(bm + lr) * K + lc;
    const float* Bp = B + (size_t)(bn + lr) * K + lc;

    float acc[8][8];
#pragma unroll
    for (int i = 0; i < 8; i++)
#pragma unroll
        for (int j = 0; j < 8; j++) acc[i][j] = 0.f;

    for (int k0 = 0; k0 < K; k0 += 8) {
        float4 a4 = *(const float4*)(Ap + k0);
        float4 b4 = *(const float4*)(Bp + k0);
        __syncthreads();
        As[lc + 0][lr] = a4.x; As[lc + 1][lr] = a4.y;
        As[lc + 2][lr] = a4.z; As[lc + 3][lr] = a4.w;
        Bs[lc + 0][lr] = b4.x; Bs[lc + 1][lr] = b4.y;
        Bs[lc + 2][lr] = b4.z; Bs[lc + 3][lr] = b4.w;
        __syncthreads();
#pragma unroll
        for (int kk = 0; kk < 8; kk++) {
            float4 a0 = *(const float4*)&As[kk][ty * 4];
            float4 a1 = *(const float4*)&As[kk][ty * 4 + 64];
            float4 b0 = *(const float4*)&Bs[kk][tx * 4];
            float4 b1 = *(const float4*)&Bs[kk][tx * 4 + 64];
            float ar[8] = {a0.x, a0.y, a0.z, a0.w, a1.x, a1.y, a1.z, a1.w};
            float br[8] = {b0.x, b0.y, b0.z, b0.w, b1.x, b1.y, b1.z, b1.w};
#pragma unroll
            for (int ii = 0; ii < 8; ii++)
#pragma unroll
                for (int jj = 0; jj < 8; jj++)
                    acc[ii][jj] += ar[ii] * br[jj];
        }
    }

#pragma unroll
    for (int half = 0; half < 2; half++) {
#pragma unroll
        for (int r = 0; r < 4; r++) {
            int ii = half * 4 + r;
            size_t row = (size_t)(bm + half * 64 + ty * 4 + r);
            float* Cp = C + row * N + bn;
            float4 c0 = make_float4(acc[ii][0], acc[ii][1], acc[ii][2], acc[ii][3]);
            float4 c1 = make_float4(acc[ii][4], acc[ii][5], acc[ii][6], acc[ii][7]);
            *(float4*)(Cp + tx * 4) = c0;
            *(float4*)(Cp + 64 + tx * 4) = c1;
        }
    }
}

// ---------------- RMSNorm (+ optional weight) + RoPE, head-major out ----------
// grid: (S, 16): y 0..7 -> Q heads, 8..11 -> K heads, 12..15 -> V heads
__global__ __launch_bounds__(256)
void norm_rope_kernel(const float* __restrict__ Qp, const float* __restrict__ Kp,
                      const float* __restrict__ Vp,
                      const float* __restrict__ cosb, const float* __restrict__ sinb,
                      const float* __restrict__ qw, const float* __restrict__ kw,
                      float* __restrict__ Qr, float* __restrict__ Kr,
                      float* __restrict__ Vr) {
    const int s = blockIdx.x;
    const int hh = blockIdx.y;
    const int d = threadIdx.x;

    const float* src;
    float* dst;
    const float* w = nullptr;
    bool do_rope = false;

    if (hh < HQ) {
        src = Qp + (size_t)s * (HQ * HD) + hh * HD;
        dst = Qr + ((size_t)hh * S_LEN + s) * HD;
        w = qw; do_rope = true;
    } else if (hh < HQ + HKV) {
        int h = hh - HQ;
        src = Kp + (size_t)s * (HKV * HD) + h * HD;
        dst = Kr + ((size_t)h * S_LEN + s) * HD;
        w = kw; do_rope = true;
    } else {
        int h = hh - HQ - HKV;
        src = Vp + (size_t)s * (HKV * HD) + h * HD;
        dst = Vr + ((size_t)h * S_LEN + s) * HD;
    }

    float x = src[d];

    __shared__ float red[8];
    __shared__ float ysh[HD];
    float v = x * x;
#pragma unroll
    for (int off = 16; off > 0; off >>= 1)
        v += __shfl_xor_sync(0xffffffffu, v, off);
    if ((d & 31) == 0) red[d >> 5] = v;
    __syncthreads();
    float tot = 0.f;
#pragma unroll
    for (int r = 0; r < 8; r++) tot += red[r];

    float rms = rsqrtf(tot * (1.0f / HD) + 1e-6f);
    float y = x * rms;
    if (w) y *= w[d];

    if (do_rope) {
        ysh[d] = y;
        __syncthreads();
        float rot = (d < HD / 2) ? -ysh[d + HD / 2] : ysh[d - HD / 2];
        y = y * cosb[(size_t)s * HD + d] + rot * sinb[(size_t)s * HD + d];
    }
    dst[d] = y;
}

// ---------------- sliding-window flash attention with softcap ----------------
// grid: (S/32, HQ), 256 threads. Thread (i = tid>>3 query row, o = tid&7).
// Thread owns dims d in {o*4 + 32*m4 .. +3 : m4=0..7} (conflict-free v reads).
#define PADW 260
#define SMEM_ATTN (3 * 32 * PADW * 4)

__global__ __launch_bounds__(256, 2)
void attn_kernel(const float* __restrict__ Q, const float* __restrict__ K,
                 const float* __restrict__ V, float* __restrict__ AO) {
    extern __shared__ float sm[];
    float* q_sh = sm;
    float* k_sh = sm + 32 * PADW;
    float* v_sh = sm + 64 * PADW;

    const int tid = threadIdx.x;
    const int h = blockIdx.y;
    const int q0 = blockIdx.x * 32;
    const float* Qh = Q + (size_t)h * S_LEN * HD;
    const float* Kh = K + (size_t)(h >> 1) * S_LEN * HD;   // n_rep = 2
    const float* Vh = V + (size_t)(h >> 1) * S_LEN * HD;

    // load Q tile [32][256]
#pragma unroll
    for (int it = 0; it < 8; it++) {
        int idx = tid + it * 256;
        int r = idx >> 6, c4 = idx & 63;
        *(float4*)(q_sh + r * PADW + c4 * 4) =
            *(const float4*)(Qh + (size_t)(q0 + r) * HD + c4 * 4);
    }

    const int i = tid >> 3;   // query row 0..31
    const int o = tid & 7;    // key-column group / dim group

    float4 acc4[8];
#pragma unroll
    for (int m4 = 0; m4 < 8; m4++) acc4[m4] = make_float4(0.f, 0.f, 0.f, 0.f);
    float m_i = -1e30f, l_i = 0.f;

    int klo = q0 - (WIN - 1);
    if (klo < 0) klo = 0;
    const int kt0 = klo & ~31;

    for (int kt = kt0; kt <= q0; kt += 32) {
        __syncthreads();   // previous tile fully consumed
#pragma unroll
        for (int it = 0; it < 8; it++) {
            int idx = tid + it * 256;
            int r = idx >> 6, c4 = idx & 63;
            size_t g = (size_t)(kt + r) * HD + c4 * 4;
            *(float4*)(k_sh + r * PADW + c4 * 4) = *(const float4*)(Kh + g);
            *(float4*)(v_sh + r * PADW + c4 * 4) = *(const float4*)(Vh + g);
        }
        __syncthreads();

        // scores: this thread computes s[i][o + 8*jj], jj=0..3
        float s0 = 0.f, s1 = 0.f, s2 = 0.f, s3 = 0.f;
        const float* qr = q_sh + i * PADW;
        const float* kr = k_sh + o * PADW;
#pragma unroll 8
        for (int d4 = 0; d4 < 64; d4++) {
            float4 qv = *(const float4*)(qr + d4 * 4);
            float4 k0v = *(const float4*)(kr + d4 * 4);
            float4 k1v = *(const float4*)(kr + 8 * PADW + d4 * 4);
            float4 k2v = *(const float4*)(kr + 16 * PADW + d4 * 4);
            float4 k3v = *(const float4*)(kr + 24 * PADW + d4 * 4);
            s0 += qv.x * k0v.x + qv.y * k0v.y + qv.z * k0v.z + qv.w * k0v.w;
            s1 += qv.x * k1v.x + qv.y * k1v.y + qv.z * k1v.z + qv.w * k1v.w;
            s2 += qv.x * k2v.x + qv.y * k2v.y + qv.z * k2v.z + qv.w * k2v.w;
            s3 += qv.x * k3v.x + qv.y * k3v.y + qv.z * k3v.z + qv.w * k3v.w;
        }

        float p[4];
        {
            float sc[4] = {s0, s1, s2, s3};
            const int qg = q0 + i;
#pragma unroll
            for (int jj = 0; jj < 4; jj++) {
                int kg = kt + o + 8 * jj;
                float scp = 50.0f * tanhf(sc[jj] * 0.02f);  // softcap
                bool ok = (kg <= qg) && (qg - kg < WIN);
                sc[jj] = ok ? scp : -1e30f;
            }
            float mt = fmaxf(fmaxf(sc[0], sc[1]), fmaxf(sc[2], sc[3]));
            mt = fmaxf(mt, __shfl_xor_sync(0xffffffffu, mt, 1));
            mt = fmaxf(mt, __shfl_xor_sync(0xffffffffu, mt, 2));
            mt = fmaxf(mt, __shfl_xor_sync(0xffffffffu, mt, 4));
            float nm = fmaxf(m_i, mt);
            float scale;
            if (nm > -1e29f) {
                scale = __expf(m_i - nm);
#pragma unroll
                for (int jj = 0; jj < 4; jj++) p[jj] = __expf(sc[jj] - nm);
                m_i = nm;
            } else {   // whole 8-group row fully masked this tile
                scale = 1.f;
                p[0] = p[1] = p[2] = p[3] = 0.f;
            }
            float ps = p[0] + p[1] + p[2] + p[3];
            ps += __shfl_xor_sync(0xffffffffu, ps, 1);
            ps += __shfl_xor_sync(0xffffffffu, ps, 2);
            ps += __shfl_xor_sync(0xffffffffu, ps, 4);
            l_i = l_i * scale + ps;
#pragma unroll
            for (int m4 = 0; m4 < 8; m4++) {
                acc4[m4].x *= scale; acc4[m4].y *= scale;
                acc4[m4].z *= scale; acc4[m4].w *= scale;
            }
        }

        // PV: acc[d] += p[j] * v[j][d]
        const int sbase = (i & 3) * 8;
#pragma unroll
        for (int jq = 0; jq < 4; jq++) {
#pragma unroll
            for (int jo = 0; jo < 8; jo++) {
                float pj = __shfl_sync(0xffffffffu, p[jq], sbase + jo);
                const float* vr = v_sh + (jq * 8 + jo) * PADW + o * 4;
#pragma unroll
                for (int m4 = 0; m4 < 8; m4++) {
                    float4 vv = *(const float4*)(vr + m4 * 32);
                    acc4[m4].x += pj * vv.x; acc4[m4].y += pj * vv.y;
                    acc4[m4].z += pj * vv.z; acc4[m4].w += pj * vv.w;
                }
            }
        }
    }

    const float inv = 1.0f / l_i;
    float* op = AO + (size_t)(q0 + i) * (HQ * HD) + h * HD + o * 4;
#pragma unroll
    for (int m4 = 0; m4 < 8; m4++) {
        float4 r;
        r.x = acc4[m4].x * inv; r.y = acc4[m4].y * inv;
        r.z = acc4[m4].z * inv; r.w = acc4[m4].w * inv;
        *(float4*)(op + m4 * 32) = r;
    }
}

// ---------------- launch ----------------
extern "C" void kernel_launch(void* const* d_in, const int* in_sizes, int n_in,
                              void* d_out, int out_size) {
    const float* hidden = (const float*)d_in[0];
    const float* cosb   = (const float*)d_in[1];
    const float* sinb   = (const float*)d_in[2];
    // d_in[3] = attention_mask: exactly the sliding window; implemented directly.
    const float* Wq = (const float*)d_in[4];
    const float* Wk = (const float*)d_in[5];
    const float* Wv = (const float*)d_in[6];
    const float* Wo = (const float*)d_in[7];
    const float* qw = (const float*)d_in[8];
    const float* kw = (const float*)d_in[9];
    float* out = (float*)d_out;

    float *Qp, *Kp, *Vp, *Qr, *Kr, *Vr, *AO;
    cudaGetSymbolAddress((void**)&Qp, g_Qp);
    cudaGetSymbolAddress((void**)&Kp, g_Kp);
    cudaGetSymbolAddress((void**)&Vp, g_Vp);
    cudaGetSymbolAddress((void**)&Qr, g_Qr);
    cudaGetSymbolAddress((void**)&Kr, g_Kr);
    cudaGetSymbolAddress((void**)&Vr, g_Vr);
    cudaGetSymbolAddress((void**)&AO, g_AO);

    cudaFuncSetAttribute((const void*)attn_kernel,
                         cudaFuncAttributeMaxDynamicSharedMemorySize, SMEM_ATTN);

    dim3 blk(256);
    // QKV projections
    sgemm_nt<<<dim3(16, 32), blk>>>(hidden, Wq, Qp, S_LEN, HQ * HD, H_DIM);
    sgemm_nt<<<dim3(8, 32), blk>>>(hidden, Wk, Kp, S_LEN, HKV * HD, H_DIM);
    sgemm_nt<<<dim3(8, 32), blk>>>(hidden, Wv, Vp, S_LEN, HKV * HD, H_DIM);
    // RMSNorm + RoPE -> head-major layouts
    norm_rope_kernel<<<dim3(S_LEN, HQ + 2 * HKV), 256>>>(
        Qp, Kp, Vp, cosb, sinb, qw, kw, Qr, Kr, Vr);
    // sliding-window attention
    attn_kernel<<<dim3(S_LEN / 32, HQ), 256, SMEM_ATTN>>>(Qr, Kr, Vr, AO);
    // output projection
    sgemm_nt<<<dim3(16, 32), blk>>>(AO, Wo, out, S_LEN, H_DIM, H_DIM);
}

// round 4
// speedup vs baseline: 1.5030x; 1.5030x over previous
#include <cuda_runtime.h>
#include <cuda_bf16.h>
#include <math.h>
#include <stdint.h>

#define S_LEN 4096
#define H_DIM 2048
#define HQ 8
#define HKV 4
#define HD 256
#define WIN 1024

// ================= portable PTX helpers (baseline ISA only) =================
__device__ __forceinline__ uint32_t smem_u32(const void* p) {
    uint32_t a;
    asm("{ .reg .u64 t; cvta.to.shared.u64 t, %1; cvt.u32.u64 %0, t; }"
        : "=r"(a) : "l"(p));
    return a;
}

#define CP_ASYNC16(dst_u32, src_ptr) \
    asm volatile("cp.async.cg.shared.global [%0], [%1], 16;" \
                 :: "r"(dst_u32), "l"(src_ptr) : "memory")
#define CP_COMMIT() asm volatile("cp.async.commit_group;" ::: "memory")
#define CP_WAIT1()  asm volatile("cp.async.wait_group 1;" ::: "memory")

__device__ __forceinline__ void mma16816(float* d, const uint32_t* a,
                                         uint32_t b0, uint32_t b1) {
    asm volatile(
        "mma.sync.aligned.m16n8k16.row.col.f32.bf16.bf16.f32 "
        "{%0,%1,%2,%3}, {%4,%5,%6,%7}, {%8,%9}, {%0,%1,%2,%3};"
        : "+f"(d[0]), "+f"(d[1]), "+f"(d[2]), "+f"(d[3])
        : "r"(a[0]), "r"(a[1]), "r"(a[2]), "r"(a[3]), "r"(b0), "r"(b1));
}

// ================= scratch (device globals) =================
__device__ float g_Qp[S_LEN * (HQ * HD)];
__device__ float g_Kp[S_LEN * (HKV * HD)];
__device__ float g_Vp[S_LEN * (HKV * HD)];
__device__ float g_Qr[HQ * S_LEN * HD];
__device__ float g_Kr[HKV * S_LEN * HD];
__device__ float g_Vr[HKV * S_LEN * HD];
__device__ float g_AO[S_LEN * (HQ * HD)];

__device__ __nv_bfloat16 g_hid_h[S_LEN * H_DIM];
__device__ __nv_bfloat16 g_hid_l[S_LEN * H_DIM];
__device__ __nv_bfloat16 g_wq_h[HQ * HD * H_DIM];
__device__ __nv_bfloat16 g_wq_l[HQ * HD * H_DIM];
__device__ __nv_bfloat16 g_wk_h[HKV * HD * H_DIM];
__device__ __nv_bfloat16 g_wk_l[HKV * HD * H_DIM];
__device__ __nv_bfloat16 g_wv_h[HKV * HD * H_DIM];
__device__ __nv_bfloat16 g_wv_l[HKV * HD * H_DIM];
__device__ __nv_bfloat16 g_wo_h[H_DIM * HQ * HD];
__device__ __nv_bfloat16 g_wo_l[H_DIM * HQ * HD];
__device__ __nv_bfloat16 g_ao_h[S_LEN * HQ * HD];
__device__ __nv_bfloat16 g_ao_l[S_LEN * HQ * HD];

// ================= fp32 -> bf16 hi/lo split =================
__global__ __launch_bounds__(256)
void cvt_hilo(const float4* __restrict__ x, __nv_bfloat16* __restrict__ hi,
              __nv_bfloat16* __restrict__ lo, int n4) {
    int i = blockIdx.x * blockDim.x + threadIdx.x;
    if (i >= n4) return;
    float4 v = x[i];
    union { ushort4 u; __nv_bfloat16 b[4]; } H, L;
    H.b[0] = __float2bfloat16(v.x);
    H.b[1] = __float2bfloat16(v.y);
    H.b[2] = __float2bfloat16(v.z);
    H.b[3] = __float2bfloat16(v.w);
    L.b[0] = __float2bfloat16(v.x - __bfloat162float(H.b[0]));
    L.b[1] = __float2bfloat16(v.y - __bfloat162float(H.b[1]));
    L.b[2] = __float2bfloat16(v.z - __bfloat162float(H.b[2]));
    L.b[3] = __float2bfloat16(v.w - __bfloat162float(H.b[3]));
    *(ushort4*)(hi + 4 * (size_t)i) = H.u;
    *(ushort4*)(lo + 4 * (size_t)i) = L.u;
}

// ================= HMMA bf16x3 GEMM: C[M,N] = A[M,K] @ B[N,K]^T ============
// CTA 128x128, 128 threads (4 warps, 2x2), warp tile 64x64, BK=32,
// cp.async double-buffered. Smem rows padded to 80B -> conflict-free lds.
#define PITCH 80            // bytes per 32-col bf16 row (40 bf16)
#define MATB  10240         // 128 rows * 80B, one matrix tile
#define STAGE (4 * MATB)    // Ah, Al, Bh, Bl
#define SMEM_GEMM (2 * STAGE)

__global__ __launch_bounds__(128, 2)
void gemm_bf16x3(const __nv_bfloat16* __restrict__ Ah, const __nv_bfloat16* __restrict__ Al,
                 const __nv_bfloat16* __restrict__ Bh, const __nv_bfloat16* __restrict__ Bl,
                 float* __restrict__ C, int N, int K) {
    extern __shared__ char smemc[];
    const uint32_t sb = smem_u32(smemc);
    const int tid = threadIdx.x;
    const int lane = tid & 31;
    const int w = tid >> 5;
    const int wm = (w >> 1) * 64;     // warp row origin in tile
    const int wn = (w & 1) * 64;      // warp col origin in tile
    const int lr = lane >> 2;         // 0..7
    const int lc = lane & 3;          // 0..3
    const int bm = blockIdx.y * 128;
    const int bn = blockIdx.x * 128;
    const int nkb = K / 32;

    const __nv_bfloat16* mats[4] = {Ah, Al, Bh, Bl};
    const int rowoff[4] = {bm, bm, bn, bn};

    // ---- async stage loader: 16 cp.async per thread ----
    auto load_stage = [&](int buf, int kblk) {
        const uint32_t st = sb + buf * STAGE;
#pragma unroll
        for (int m = 0; m < 4; m++) {
            const __nv_bfloat16* src = mats[m] + (size_t)rowoff[m] * K + kblk;
            const uint32_t dstb = st + m * MATB;
#pragma unroll
            for (int i = 0; i < 4; i++) {
                int flat = tid + i * 128;
                int r = flat >> 2, c = flat & 3;
                CP_ASYNC16(dstb + r * PITCH + c * 16, src + (size_t)r * K + c * 8);
            }
        }
    };

    float acc[4][8][4];
#pragma unroll
    for (int i = 0; i < 4; i++)
#pragma unroll
        for (int j = 0; j < 8; j++)
#pragma unroll
            for (int q = 0; q < 4; q++) acc[i][j][q] = 0.f;

    load_stage(0, 0); CP_COMMIT();
    load_stage(1, 32); CP_COMMIT();

    for (int kb = 0; kb < nkb; kb++) {
        CP_WAIT1();
        __syncthreads();
        const char* st = smemc + (kb & 1) * STAGE;

#pragma unroll
        for (int kk = 0; kk < 2; kk++) {
            uint32_t ah[4][4], al[4][4];
#pragma unroll
            for (int i = 0; i < 4; i++) {
                const char* ab = st + (wm + i * 16 + lr) * PITCH + kk * 32 + lc * 4;
                ah[i][0] = *(const uint32_t*)(ab);
                ah[i][1] = *(const uint32_t*)(ab + 8 * PITCH);
                ah[i][2] = *(const uint32_t*)(ab + 16);
                ah[i][3] = *(const uint32_t*)(ab + 8 * PITCH + 16);
                al[i][0] = *(const uint32_t*)(ab + MATB);
                al[i][1] = *(const uint32_t*)(ab + MATB + 8 * PITCH);
                al[i][2] = *(const uint32_t*)(ab + MATB + 16);
                al[i][3] = *(const uint32_t*)(ab + MATB + 8 * PITCH + 16);
            }
#pragma unroll
            for (int j = 0; j < 8; j++) {
                const char* bb = st + 2 * MATB + (wn + j * 8 + lr) * PITCH + kk * 32 + lc * 4;
                uint32_t bh0 = *(const uint32_t*)(bb);
                uint32_t bh1 = *(const uint32_t*)(bb + 16);
                uint32_t bl0 = *(const uint32_t*)(bb + MATB);
                uint32_t bl1 = *(const uint32_t*)(bb + MATB + 16);
#pragma unroll
                for (int i = 0; i < 4; i++) {
                    mma16816(acc[i][j], ah[i], bh0, bh1);
                    mma16816(acc[i][j], ah[i], bl0, bl1);
                    mma16816(acc[i][j], al[i], bh0, bh1);
                }
            }
        }
        __syncthreads();
        if (kb + 2 < nkb) load_stage(kb & 1, (kb + 2) * 32);
        CP_COMMIT();
    }

    // ---- epilogue: direct fp32 stores ----
#pragma unroll
    for (int i = 0; i < 4; i++) {
        const int r0 = bm + wm + i * 16 + lr;
#pragma unroll
        for (int j = 0; j < 8; j++) {
            const int c0 = bn + wn + j * 8 + lc * 2;
            *(float2*)(C + (size_t)r0 * N + c0) = make_float2(acc[i][j][0], acc[i][j][1]);
            *(float2*)(C + (size_t)(r0 + 8) * N + c0) = make_float2(acc[i][j][2], acc[i][j][3]);
        }
    }
}

// ================= RMSNorm + RoPE =================
__global__ __launch_bounds__(256)
void norm_rope_kernel(const float* __restrict__ Qp, const float* __restrict__ Kp,
                      const float* __restrict__ Vp,
                      const float* __restrict__ cosb, const float* __restrict__ sinb,
                      const float* __restrict__ qw, const float* __restrict__ kw,
                      float* __restrict__ Qr, float* __restrict__ Kr,
                      float* __restrict__ Vr) {
    const int s = blockIdx.x;
    const int hh = blockIdx.y;
    const int d = threadIdx.x;

    const float* src;
    float* dst;
    const float* w = nullptr;
    bool do_rope = false;

    if (hh < HQ) {
        src = Qp + (size_t)s * (HQ * HD) + hh * HD;
        dst = Qr + ((size_t)hh * S_LEN + s) * HD;
        w = qw; do_rope = true;
    } else if (hh < HQ + HKV) {
        int h = hh - HQ;
        src = Kp + (size_t)s * (HKV * HD) + h * HD;
        dst = Kr + ((size_t)h * S_LEN + s) * HD;
        w = kw; do_rope = true;
    } else {
        int h = hh - HQ - HKV;
        src = Vp + (size_t)s * (HKV * HD) + h * HD;
        dst = Vr + ((size_t)h * S_LEN + s) * HD;
    }

    float x = src[d];

    __shared__ float red[8];
    __shared__ float ysh[HD];
    float v = x * x;
#pragma unroll
    for (int off = 16; off > 0; off >>= 1)
        v += __shfl_xor_sync(0xffffffffu, v, off);
    if ((d & 31) == 0) red[d >> 5] = v;
    __syncthreads();
    float tot = 0.f;
#pragma unroll
    for (int r = 0; r < 8; r++) tot += red[r];

    float rms = rsqrtf(tot * (1.0f / HD) + 1e-6f);
    float y = x * rms;
    if (w) y *= w[d];

    if (do_rope) {
        ysh[d] = y;
        __syncthreads();
        float rot = (d < HD / 2) ? -ysh[d + HD / 2] : ysh[d - HD / 2];
        y = y * cosb[(size_t)s * HD + d] + rot * sinb[(size_t)s * HD + d];
    }
    dst[d] = y;
}

// ================= attention (fp32 flash, sliding window + softcap) ========
#define PADW 260
#define SMEM_ATTN (3 * 32 * PADW * 4)

__global__ __launch_bounds__(256, 2)
void attn_kernel(const float* __restrict__ Q, const float* __restrict__ K,
                 const float* __restrict__ V, float* __restrict__ AO) {
    extern __shared__ float sm[];
    float* q_sh = sm;
    float* k_sh = sm + 32 * PADW;
    float* v_sh = sm + 64 * PADW;

    const int tid = threadIdx.x;
    const int h = blockIdx.y;
    const int q0 = blockIdx.x * 32;
    const float* Qh = Q + (size_t)h * S_LEN * HD;
    const float* Kh = K + (size_t)(h >> 1) * S_LEN * HD;
    const float* Vh = V + (size_t)(h >> 1) * S_LEN * HD;

#pragma unroll
    for (int it = 0; it < 8; it++) {
        int idx = tid + it * 256;
        int r = idx >> 6, c4 = idx & 63;
        *(float4*)(q_sh + r * PADW + c4 * 4) =
            *(const float4*)(Qh + (size_t)(q0 + r) * HD + c4 * 4);
    }

    const int i = tid >> 3;
    const int o = tid & 7;

    float4 acc4[8];
#pragma unroll
    for (int m4 = 0; m4 < 8; m4++) acc4[m4] = make_float4(0.f, 0.f, 0.f, 0.f);
    float m_i = -1e30f, l_i = 0.f;

    int klo = q0 - (WIN - 1);
    if (klo < 0) klo = 0;
    const int kt0 = klo & ~31;

    for (int kt = kt0; kt <= q0; kt += 32) {
        __syncthreads();
#pragma unroll
        for (int it = 0; it < 8; it++) {
            int idx = tid + it * 256;
            int r = idx >> 6, c4 = idx & 63;
            size_t g = (size_t)(kt + r) * HD + c4 * 4;
            *(float4*)(k_sh + r * PADW + c4 * 4) = *(const float4*)(Kh + g);
            *(float4*)(v_sh + r * PADW + c4 * 4) = *(const float4*)(Vh + g);
        }
        __syncthreads();

        float s0 = 0.f, s1 = 0.f, s2 = 0.f, s3 = 0.f;
        const float* qr = q_sh + i * PADW;
        const float* kr = k_sh + o * PADW;
#pragma unroll 8
        for (int d4 = 0; d4 < 64; d4++) {
            float4 qv = *(const float4*)(qr + d4 * 4);
            float4 k0v = *(const float4*)(kr + d4 * 4);
            float4 k1v = *(const float4*)(kr + 8 * PADW + d4 * 4);
            float4 k2v = *(const float4*)(kr + 16 * PADW + d4 * 4);
            float4 k3v = *(const float4*)(kr + 24 * PADW + d4 * 4);
            s0 += qv.x * k0v.x + qv.y * k0v.y + qv.z * k0v.z + qv.w * k0v.w;
            s1 += qv.x * k1v.x + qv.y * k1v.y + qv.z * k1v.z + qv.w * k1v.w;
            s2 += qv.x * k2v.x + qv.y * k2v.y + qv.z * k2v.z + qv.w * k2v.w;
            s3 += qv.x * k3v.x + qv.y * k3v.y + qv.z * k3v.z + qv.w * k3v.w;
        }

        float p[4];
        {
            float sc[4] = {s0, s1, s2, s3};
            const int qg = q0 + i;
#pragma unroll
            for (int jj = 0; jj < 4; jj++) {
                int kg = kt + o + 8 * jj;
                float scp = 50.0f * tanhf(sc[jj] * 0.02f);
                bool ok = (kg <= qg) && (qg - kg < WIN);
                sc[jj] = ok ? scp : -1e30f;
            }
            float mt = fmaxf(fmaxf(sc[0], sc[1]), fmaxf(sc[2], sc[3]));
            mt = fmaxf(mt, __shfl_xor_sync(0xffffffffu, mt, 1));
            mt = fmaxf(mt, __shfl_xor_sync(0xffffffffu, mt, 2));
            mt = fmaxf(mt, __shfl_xor_sync(0xffffffffu, mt, 4));
            float nm = fmaxf(m_i, mt);
            float scale;
            if (nm > -1e29f) {
                scale = __expf(m_i - nm);
#pragma unroll
                for (int jj = 0; jj < 4; jj++) p[jj] = __expf(sc[jj] - nm);
                m_i = nm;
            } else {
                scale = 1.f;
                p[0] = p[1] = p[2] = p[3] = 0.f;
            }
            float ps = p[0] + p[1] + p[2] + p[3];
            ps += __shfl_xor_sync(0xffffffffu, ps, 1);
            ps += __shfl_xor_sync(0xffffffffu, ps, 2);
            ps += __shfl_xor_sync(0xffffffffu, ps, 4);
            l_i = l_i * scale + ps;
#pragma unroll
            for (int m4 = 0; m4 < 8; m4++) {
                acc4[m4].x *= scale; acc4[m4].y *= scale;
                acc4[m4].z *= scale; acc4[m4].w *= scale;
            }
        }

        const int sbase = (i & 3) * 8;
#pragma unroll
        for (int jq = 0; jq < 4; jq++) {
#pragma unroll
            for (int jo = 0; jo < 8; jo++) {
                float pj = __shfl_sync(0xffffffffu, p[jq], sbase + jo);
                const float* vr = v_sh + (jq * 8 + jo) * PADW + o * 4;
#pragma unroll
                for (int m4 = 0; m4 < 8; m4++) {
                    float4 vv = *(const float4*)(vr + m4 * 32);
                    acc4[m4].x += pj * vv.x; acc4[m4].y += pj * vv.y;
                    acc4[m4].z += pj * vv.z; acc4[m4].w += pj * vv.w;
                }
            }
        }
    }

    const float inv = 1.0f / l_i;
    float* op = AO + (size_t)(q0 + i) * (HQ * HD) + h * HD + o * 4;
#pragma unroll
    for (int m4 = 0; m4 < 8; m4++) {
        float4 r;
        r.x = acc4[m4].x * inv; r.y = acc4[m4].y * inv;
        r.z = acc4[m4].z * inv; r.w = acc4[m4].w * inv;
        *(float4*)(op + m4 * 32) = r;
    }
}

// ================= launch =================
extern "C" void kernel_launch(void* const* d_in, const int* in_sizes, int n_in,
                              void* d_out, int out_size) {
    const float* hidden = (const float*)d_in[0];
    const float* cosb   = (const float*)d_in[1];
    const float* sinb   = (const float*)d_in[2];
    // d_in[3] = attention_mask (sliding window, implemented analytically)
    const float* Wq = (const float*)d_in[4];
    const float* Wk = (const float*)d_in[5];
    const float* Wv = (const float*)d_in[6];
    const float* Wo = (const float*)d_in[7];
    const float* qw = (const float*)d_in[8];
    const float* kw = (const float*)d_in[9];
    float* out = (float*)d_out;

    float *Qp, *Kp, *Vp, *Qr, *Kr, *Vr, *AO;
    cudaGetSymbolAddress((void**)&Qp, g_Qp);
    cudaGetSymbolAddress((void**)&Kp, g_Kp);
    cudaGetSymbolAddress((void**)&Vp, g_Vp);
    cudaGetSymbolAddress((void**)&Qr, g_Qr);
    cudaGetSymbolAddress((void**)&Kr, g_Kr);
    cudaGetSymbolAddress((void**)&Vr, g_Vr);
    cudaGetSymbolAddress((void**)&AO, g_AO);

    __nv_bfloat16 *hidh, *hidl, *wqh, *wql, *wkh, *wkl, *wvh, *wvl, *woh, *wol, *aoh, *aol;
    cudaGetSymbolAddress((void**)&hidh, g_hid_h);
    cudaGetSymbolAddress((void**)&hidl, g_hid_l);
    cudaGetSymbolAddress((void**)&wqh, g_wq_h);
    cudaGetSymbolAddress((void**)&wql, g_wq_l);
    cudaGetSymbolAddress((void**)&wkh, g_wk_h);
    cudaGetSymbolAddress((void**)&wkl, g_wk_l);
    cudaGetSymbolAddress((void**)&wvh, g_wv_h);
    cudaGetSymbolAddress((void**)&wvl, g_wv_l);
    cudaGetSymbolAddress((void**)&woh, g_wo_h);
    cudaGetSymbolAddress((void**)&wol, g_wo_l);
    cudaGetSymbolAddress((void**)&aoh, g_ao_h);
    cudaGetSymbolAddress((void**)&aol, g_ao_l);

    cudaFuncSetAttribute((const void*)attn_kernel,
                         cudaFuncAttributeMaxDynamicSharedMemorySize, SMEM_ATTN);
    cudaFuncSetAttribute((const void*)gemm_bf16x3,
                         cudaFuncAttributeMaxDynamicSharedMemorySize, SMEM_GEMM);

    // fp32 -> bf16 hi/lo splits
    cvt_hilo<<<8192, 256>>>((const float4*)hidden, hidh, hidl, (S_LEN * H_DIM) / 4);
    cvt_hilo<<<4096, 256>>>((const float4*)Wq, wqh, wql, (HQ * HD * H_DIM) / 4);
    cvt_hilo<<<2048, 256>>>((const float4*)Wk, wkh, wkl, (HKV * HD * H_DIM) / 4);
    cvt_hilo<<<2048, 256>>>((const float4*)Wv, wvh, wvl, (HKV * HD * H_DIM) / 4);
    cvt_hilo<<<4096, 256>>>((const float4*)Wo, woh, wol, (H_DIM * HQ * HD) / 4);

    // QKV projections (HMMA tensor cores)
    gemm_bf16x3<<<dim3(16, 32), 128, SMEM_GEMM>>>(hidh, hidl, wqh, wql, Qp, HQ * HD, H_DIM);
    gemm_bf16x3<<<dim3(8, 32), 128, SMEM_GEMM>>>(hidh, hidl, wkh, wkl, Kp, HKV * HD, H_DIM);
    gemm_bf16x3<<<dim3(8, 32), 128, SMEM_GEMM>>>(hidh, hidl, wvh, wvl, Vp, HKV * HD, H_DIM);

    norm_rope_kernel<<<dim3(S_LEN, HQ + 2 * HKV), 256>>>(
        Qp, Kp, Vp, cosb, sinb, qw, kw, Qr, Kr, Vr);

    attn_kernel<<<dim3(S_LEN / 32, HQ), 256, SMEM_ATTN>>>(Qr, Kr, Vr, AO);

    // output projection
    cvt_hilo<<<8192, 256>>>((const float4*)AO, aoh, aol, (S_LEN * HQ * HD) / 4);
    gemm_bf16x3<<<dim3(16, 32), 128, SMEM_GEMM>>>(aoh, aol, woh, wol, out, H_DIM, H_DIM);
}

// round 5
// speedup vs baseline: 3.3747x; 2.2453x over previous
#include <cuda_runtime.h>
#include <cuda_bf16.h>
#include <math.h>
#include <stdint.h>

#define S_LEN 4096
#define H_DIM 2048
#define HQ 8
#define HKV 4
#define HD 256
#define WIN 1024

// ================= portable PTX helpers (baseline ISA only) =================
__device__ __forceinline__ uint32_t smem_u32(const void* p) {
    uint32_t a;
    asm("{ .reg .u64 t; cvta.to.shared.u64 t, %1; cvt.u32.u64 %0, t; }"
        : "=r"(a) : "l"(p));
    return a;
}

#define CP_ASYNC16(dst_u32, src_ptr) \
    asm volatile("cp.async.cg.shared.global [%0], [%1], 16;" \
                 :: "r"(dst_u32), "l"(src_ptr) : "memory")
#define CP_COMMIT() asm volatile("cp.async.commit_group;" ::: "memory")
#define CP_WAIT1()  asm volatile("cp.async.wait_group 1;" ::: "memory")

__device__ __forceinline__ void mma16816(float* d, const uint32_t* a,
                                         uint32_t b0, uint32_t b1) {
    asm volatile(
        "mma.sync.aligned.m16n8k16.row.col.f32.bf16.bf16.f32 "
        "{%0,%1,%2,%3}, {%4,%5,%6,%7}, {%8,%9}, {%0,%1,%2,%3};"
        : "+f"(d[0]), "+f"(d[1]), "+f"(d[2]), "+f"(d[3])
        : "r"(a[0]), "r"(a[1]), "r"(a[2]), "r"(a[3]), "r"(b0), "r"(b1));
}

__device__ __forceinline__ void ldsm4(uint32_t* r, uint32_t addr) {
    asm volatile("ldmatrix.sync.aligned.m8n8.x4.shared.b16 {%0,%1,%2,%3}, [%4];"
                 : "=r"(r[0]), "=r"(r[1]), "=r"(r[2]), "=r"(r[3]) : "r"(addr));
}
__device__ __forceinline__ void ldsm4t(uint32_t* r, uint32_t addr) {
    asm volatile("ldmatrix.sync.aligned.m8n8.x4.trans.shared.b16 {%0,%1,%2,%3}, [%4];"
                 : "=r"(r[0]), "=r"(r[1]), "=r"(r[2]), "=r"(r[3]) : "r"(addr));
}

__device__ __forceinline__ uint32_t pack2bf(float a, float b) {
    __nv_bfloat162 t = __floats2bfloat162_rn(a, b);
    return *(uint32_t*)&t;
}

// ================= scratch (device globals) =================
__device__ float g_Qp[S_LEN * (HQ * HD)];
__device__ float g_Kp[S_LEN * (HKV * HD)];
__device__ float g_Vp[S_LEN * (HKV * HD)];
__device__ float g_AO[S_LEN * (HQ * HD)];

__device__ __nv_bfloat16 g_hid_h[S_LEN * H_DIM];
__device__ __nv_bfloat16 g_hid_l[S_LEN * H_DIM];
__device__ __nv_bfloat16 g_wq_h[HQ * HD * H_DIM];
__device__ __nv_bfloat16 g_wq_l[HQ * HD * H_DIM];
__device__ __nv_bfloat16 g_wk_h[HKV * HD * H_DIM];
__device__ __nv_bfloat16 g_wk_l[HKV * HD * H_DIM];
__device__ __nv_bfloat16 g_wv_h[HKV * HD * H_DIM];
__device__ __nv_bfloat16 g_wv_l[HKV * HD * H_DIM];
__device__ __nv_bfloat16 g_wo_h[H_DIM * HQ * HD];
__device__ __nv_bfloat16 g_wo_l[H_DIM * HQ * HD];
__device__ __nv_bfloat16 g_ao_h[S_LEN * HQ * HD];
__device__ __nv_bfloat16 g_ao_l[S_LEN * HQ * HD];

// attention operands, bf16 hi/lo, [head][S][HD]
__device__ __nv_bfloat16 g_qr_h[HQ * S_LEN * HD];
__device__ __nv_bfloat16 g_qr_l[HQ * S_LEN * HD];
__device__ __nv_bfloat16 g_kr_h[HKV * S_LEN * HD];
__device__ __nv_bfloat16 g_kr_l[HKV * S_LEN * HD];
__device__ __nv_bfloat16 g_vr_h[HKV * S_LEN * HD];
__device__ __nv_bfloat16 g_vr_l[HKV * S_LEN * HD];

// ================= fp32 -> bf16 hi/lo split =================
__global__ __launch_bounds__(256)
void cvt_hilo(const float4* __restrict__ x, __nv_bfloat16* __restrict__ hi,
              __nv_bfloat16* __restrict__ lo, int n4) {
    int i = blockIdx.x * blockDim.x + threadIdx.x;
    if (i >= n4) return;
    float4 v = x[i];
    union { ushort4 u; __nv_bfloat16 b[4]; } H, L;
    H.b[0] = __float2bfloat16(v.x);
    H.b[1] = __float2bfloat16(v.y);
    H.b[2] = __float2bfloat16(v.z);
    H.b[3] = __float2bfloat16(v.w);
    L.b[0] = __float2bfloat16(v.x - __bfloat162float(H.b[0]));
    L.b[1] = __float2bfloat16(v.y - __bfloat162float(H.b[1]));
    L.b[2] = __float2bfloat16(v.z - __bfloat162float(H.b[2]));
    L.b[3] = __float2bfloat16(v.w - __bfloat162float(H.b[3]));
    *(ushort4*)(hi + 4 * (size_t)i) = H.u;
    *(ushort4*)(lo + 4 * (size_t)i) = L.u;
}

// ================= HMMA bf16x3 GEMM: C[M,N] = A[M,K] @ B[N,K]^T ============
// CTA 128x128, 128 threads (4 warps, 2x2), warp tile 64x64, BK=32,
// cp.async double-buffered, ldmatrix fragment loads.
#define PITCH 80
#define MATB  10240
#define STAGE (4 * MATB)
#define SMEM_GEMM (2 * STAGE)

__global__ __launch_bounds__(128, 2)
void gemm_bf16x3(const __nv_bfloat16* __restrict__ Ah, const __nv_bfloat16* __restrict__ Al,
                 const __nv_bfloat16* __restrict__ Bh, const __nv_bfloat16* __restrict__ Bl,
                 float* __restrict__ C, int N, int K) {
    extern __shared__ char smemc[];
    const uint32_t sb = smem_u32(smemc);
    const int tid = threadIdx.x;
    const int lane = tid & 31;
    const int w = tid >> 5;
    const int wm = (w >> 1) * 64;
    const int wn = (w & 1) * 64;
    const int bm = blockIdx.y * 128;
    const int bn = blockIdx.x * 128;
    const int nkb = K / 32;

    const __nv_bfloat16* mats[4] = {Ah, Al, Bh, Bl};
    const int rowoff[4] = {bm, bm, bn, bn};

    auto load_stage = [&](int buf, int kblk) {
        const uint32_t st = sb + buf * STAGE;
#pragma unroll
        for (int m = 0; m < 4; m++) {
            const __nv_bfloat16* src = mats[m] + (size_t)rowoff[m] * K + kblk;
            const uint32_t dstb = st + m * MATB;
#pragma unroll
            for (int i = 0; i < 4; i++) {
                int flat = tid + i * 128;
                int r = flat >> 2, c = flat & 3;
                CP_ASYNC16(dstb + r * PITCH + c * 16, src + (size_t)r * K + c * 8);
            }
        }
    };

    float acc[4][8][4];
#pragma unroll
    for (int i = 0; i < 4; i++)
#pragma unroll
        for (int j = 0; j < 8; j++)
#pragma unroll
            for (int q = 0; q < 4; q++) acc[i][j][q] = 0.f;

    load_stage(0, 0); CP_COMMIT();
    load_stage(1, 32); CP_COMMIT();

    // ldmatrix lane offsets
    const int aro = (lane & 7) + 8 * ((lane >> 3) & 1);   // A: row within 16
    const int aco = (lane >> 4) * 16;                     // A: k-byte sub
    const int bro = (lane & 7) + 8 * ((lane >> 4) & 1);   // B: n row within 16
    const int bco = ((lane >> 3) & 1) * 16;               // B: k-byte sub

    for (int kb = 0; kb < nkb; kb++) {
        CP_WAIT1();
        __syncthreads();
        const uint32_t st = sb + (kb & 1) * STAGE;

#pragma unroll
        for (int kk = 0; kk < 2; kk++) {
            uint32_t ah[4][4], al[4][4];
#pragma unroll
            for (int i = 0; i < 4; i++) {
                uint32_t ab = st + (wm + i * 16 + aro) * PITCH + kk * 32 + aco;
                ldsm4(ah[i], ab);
                ldsm4(al[i], ab + MATB);
            }
#pragma unroll
            for (int jp = 0; jp < 4; jp++) {
                uint32_t bh[4], bl[4];
                uint32_t bb = st + 2 * MATB + (wn + jp * 16 + bro) * PITCH + kk * 32 + bco;
                ldsm4(bh, bb);
                ldsm4(bl, bb + MATB);
#pragma unroll
                for (int i = 0; i < 4; i++) {
                    mma16816(acc[i][2 * jp], ah[i], bh[0], bh[1]);
                    mma16816(acc[i][2 * jp], ah[i], bl[0], bl[1]);
                    mma16816(acc[i][2 * jp], al[i], bh[0], bh[1]);
                    mma16816(acc[i][2 * jp + 1], ah[i], bh[2], bh[3]);
                    mma16816(acc[i][2 * jp + 1], ah[i], bl[2], bl[3]);
                    mma16816(acc[i][2 * jp + 1], al[i], bh[2], bh[3]);
                }
            }
        }
        __syncthreads();
        if (kb + 2 < nkb) load_stage(kb & 1, (kb + 2) * 32);
        CP_COMMIT();
    }

    const int lr = lane >> 2;
    const int lc = lane & 3;
#pragma unroll
    for (int i = 0; i < 4; i++) {
        const int r0 = bm + wm + i * 16 + lr;
#pragma unroll
        for (int j = 0; j < 8; j++) {
            const int c0 = bn + wn + j * 8 + lc * 2;
            *(float2*)(C + (size_t)r0 * N + c0) = make_float2(acc[i][j][0], acc[i][j][1]);
            *(float2*)(C + (size_t)(r0 + 8) * N + c0) = make_float2(acc[i][j][2], acc[i][j][3]);
        }
    }
}

// ================= RMSNorm + RoPE -> bf16 hi/lo head-major =================
__global__ __launch_bounds__(256)
void norm_rope_kernel(const float* __restrict__ Qp, const float* __restrict__ Kp,
                      const float* __restrict__ Vp,
                      const float* __restrict__ cosb, const float* __restrict__ sinb,
                      const float* __restrict__ qw, const float* __restrict__ kw,
                      __nv_bfloat16* __restrict__ Qrh, __nv_bfloat16* __restrict__ Qrl,
                      __nv_bfloat16* __restrict__ Krh, __nv_bfloat16* __restrict__ Krl,
                      __nv_bfloat16* __restrict__ Vrh, __nv_bfloat16* __restrict__ Vrl) {
    const int s = blockIdx.x;
    const int hh = blockIdx.y;
    const int d = threadIdx.x;

    const float* src;
    __nv_bfloat16 *dsth, *dstl;
    const float* w = nullptr;
    bool do_rope = false;

    if (hh < HQ) {
        src = Qp + (size_t)s * (HQ * HD) + hh * HD;
        dsth = Qrh + ((size_t)hh * S_LEN + s) * HD;
        dstl = Qrl + ((size_t)hh * S_LEN + s) * HD;
        w = qw; do_rope = true;
    } else if (hh < HQ + HKV) {
        int h = hh - HQ;
        src = Kp + (size_t)s * (HKV * HD) + h * HD;
        dsth = Krh + ((size_t)h * S_LEN + s) * HD;
        dstl = Krl + ((size_t)h * S_LEN + s) * HD;
        w = kw; do_rope = true;
    } else {
        int h = hh - HQ - HKV;
        src = Vp + (size_t)s * (HKV * HD) + h * HD;
        dsth = Vrh + ((size_t)h * S_LEN + s) * HD;
        dstl = Vrl + ((size_t)h * S_LEN + s) * HD;
    }

    float x = src[d];

    __shared__ float red[8];
    __shared__ float ysh[HD];
    float v = x * x;
#pragma unroll
    for (int off = 16; off > 0; off >>= 1)
        v += __shfl_xor_sync(0xffffffffu, v, off);
    if ((d & 31) == 0) red[d >> 5] = v;
    __syncthreads();
    float tot = 0.f;
#pragma unroll
    for (int r = 0; r < 8; r++) tot += red[r];

    float rms = rsqrtf(tot * (1.0f / HD) + 1e-6f);
    float y = x * rms;
    if (w) y *= w[d];

    if (do_rope) {
        ysh[d] = y;
        __syncthreads();
        float rot = (d < HD / 2) ? -ysh[d + HD / 2] : ysh[d - HD / 2];
        y = y * cosb[(size_t)s * HD + d] + rot * sinb[(size_t)s * HD + d];
    }
    __nv_bfloat16 hb = __float2bfloat16(y);
    dsth[d] = hb;
    dstl[d] = __float2bfloat16(y - __bfloat162float(hb));
}

// ================= HMMA flash attention (sliding window + softcap) =========
// Block: 64 queries, 256 threads (8 warps), key tiles of 64, 1 CTA/SM.
// QK: hi/lo 3-term; P split hi/lo, PV 3-term. fp32 softmax on fragments.
#define APITCH 528                       // 256 bf16 row + 16B pad
#define AQH_OFF 0
#define AQL_OFF 33792
#define AKH_OFF 67584
#define AKL_OFF 101376
#define AVH_OFF 135168
#define AVL_OFF 168960
#define APH_OFF 202752                   // P tile, pitch 144
#define APL_OFF 211968
#define ASTAT_OFF 221184                 // marr,larr,alpha,pm0,pm1,ps0,ps1 (64 f each)
#define SMEM_ATTN 222976

__global__ __launch_bounds__(256, 1)
void attn_mma(const __nv_bfloat16* __restrict__ Qh, const __nv_bfloat16* __restrict__ Ql,
              const __nv_bfloat16* __restrict__ Kh, const __nv_bfloat16* __restrict__ Kl,
              const __nv_bfloat16* __restrict__ Vh, const __nv_bfloat16* __restrict__ Vl,
              float* __restrict__ AO) {
    extern __shared__ char smemc[];
    const uint32_t sb = smem_u32(smemc);
    const int tid = threadIdx.x;
    const int lane = tid & 31;
    const int w = tid >> 5;
    const int h = blockIdx.y;
    const int q0 = blockIdx.x * 64;

    const __nv_bfloat16* qhp = Qh + ((size_t)h * S_LEN + q0) * HD;
    const __nv_bfloat16* qlp = Ql + ((size_t)h * S_LEN + q0) * HD;
    const __nv_bfloat16* khp = Kh + (size_t)(h >> 1) * S_LEN * HD;
    const __nv_bfloat16* klp = Kl + (size_t)(h >> 1) * S_LEN * HD;
    const __nv_bfloat16* vhp = Vh + (size_t)(h >> 1) * S_LEN * HD;
    const __nv_bfloat16* vlp = Vl + (size_t)(h >> 1) * S_LEN * HD;

    float* marr  = (float*)(smemc + ASTAT_OFF);
    float* larr  = marr + 64;
    float* alpha = marr + 128;
    float* pm0   = marr + 192;
    float* pm1   = marr + 256;
    float* ps0   = marr + 320;
    float* ps1   = marr + 384;

    if (tid < 64) { marr[tid] = -1e30f; larr[tid] = 0.f; }

    // Q tile load (64 rows x 512B per array)
    auto cpQ = [&](uint32_t off, const __nv_bfloat16* src) {
#pragma unroll
        for (int i = 0; i < 8; i++) {
            int flat = tid + i * 256;
            int r = flat >> 5, c = flat & 31;
            CP_ASYNC16(sb + off + r * APITCH + c * 16, src + (size_t)r * HD + c * 8);
        }
    };
    auto cpT = [&](uint32_t off, const __nv_bfloat16* base, int kt) {
#pragma unroll
        for (int i = 0; i < 8; i++) {
            int flat = tid + i * 256;
            int r = flat >> 5, c = flat & 31;
            CP_ASYNC16(sb + off + r * APITCH + c * 16, base + (size_t)(kt + r) * HD + c * 8);
        }
    };

    int klo = q0 - (WIN - 1);
    if (klo < 0) klo = 0;
    const int kt0 = klo & ~63;

    cpQ(AQH_OFF, qhp); cpQ(AQL_OFF, qlp);
    cpT(AKH_OFF, khp, kt0); cpT(AKL_OFF, klp, kt0);
    CP_COMMIT();

    float oacc[16][4];
#pragma unroll
    for (int i = 0; i < 16; i++)
#pragma unroll
        for (int q = 0; q < 4; q++) oacc[i][q] = 0.f;

    // lane offsets for ldmatrix
    const int aro = (lane & 7) + 8 * ((lane >> 3) & 1);
    const int aco = (lane >> 4) * 16;
    const int bro = (lane & 7) + 8 * ((lane >> 4) & 1);
    const int bco = ((lane >> 3) & 1) * 16;
    const int R  = 16 * (w >> 1);    // QK rows
    const int Ch = 32 * (w & 1);     // QK col half
    const int Rp = 16 * (w & 3);     // PV rows
    const int Dq = 128 * (w >> 2);   // PV d half
    const int rl = lane >> 2;

    __syncthreads();

    for (int kt = kt0; kt <= q0; kt += 64) {
        // V for this tile (buffer free: prev PV finished before loop-end sync)
        cpT(AVH_OFF, vhp, kt); cpT(AVL_OFF, vlp, kt);
        CP_COMMIT();
        CP_WAIT1();              // K[t] (and Q) ready; V may be in flight
        __syncthreads();

        // ---------------- QK ----------------
        float sacc[4][4];
#pragma unroll
        for (int i = 0; i < 4; i++)
#pragma unroll
            for (int q = 0; q < 4; q++) sacc[i][q] = 0.f;

#pragma unroll
        for (int ks = 0; ks < 16; ks++) {
            uint32_t aH[4], aL[4];
            uint32_t ab = sb + AQH_OFF + (R + aro) * APITCH + ks * 32 + aco;
            ldsm4(aH, ab);
            ldsm4(aL, ab + (AQL_OFF - AQH_OFF));
#pragma unroll
            for (int h2 = 0; h2 < 2; h2++) {
                uint32_t bH[4], bL[4];
                uint32_t bb = sb + AKH_OFF + (Ch + h2 * 16 + bro) * APITCH + ks * 32 + bco;
                ldsm4(bH, bb);
                ldsm4(bL, bb + (AKL_OFF - AKH_OFF));
                mma16816(sacc[2 * h2], aH, bH[0], bH[1]);
                mma16816(sacc[2 * h2], aH, bL[0], bL[1]);
                mma16816(sacc[2 * h2], aL, bH[0], bH[1]);
                mma16816(sacc[2 * h2 + 1], aH, bH[2], bH[3]);
                mma16816(sacc[2 * h2 + 1], aH, bL[2], bL[3]);
                mma16816(sacc[2 * h2 + 1], aL, bH[2], bH[3]);
            }
        }

        // softcap + mask + partial row max
        const int rlo = R + rl, rhi = R + rl + 8;
        float mx0 = -1e30f, mx1 = -1e30f;
#pragma unroll
        for (int n8 = 0; n8 < 4; n8++) {
#pragma unroll
            for (int e = 0; e < 4; e++) {
                int row = (e < 2) ? rlo : rhi;
                int kg = kt + Ch + n8 * 8 + (lane & 3) * 2 + (e & 1);
                int qg = q0 + row;
                float s = 50.0f * tanhf(sacc[n8][e] * 0.02f);
                bool ok = (kg <= qg) && (qg - kg < WIN);
                s = ok ? s : -1e30f;
                sacc[n8][e] = s;
                if (e < 2) mx0 = fmaxf(mx0, s); else mx1 = fmaxf(mx1, s);
            }
        }
        mx0 = fmaxf(mx0, __shfl_xor_sync(0xffffffffu, mx0, 1));
        mx0 = fmaxf(mx0, __shfl_xor_sync(0xffffffffu, mx0, 2));
        mx1 = fmaxf(mx1, __shfl_xor_sync(0xffffffffu, mx1, 1));
        mx1 = fmaxf(mx1, __shfl_xor_sync(0xffffffffu, mx1, 2));
        if ((lane & 3) == 0) {
            float* pmh = (w & 1) ? pm1 : pm0;
            pmh[rlo] = mx0; pmh[rhi] = mx1;
        }
        __syncthreads();

        // prefetch next K (K buffer free after QK)
        if (kt + 64 <= q0) { cpT(AKH_OFF, khp, kt + 64); cpT(AKL_OFF, klp, kt + 64); }
        CP_COMMIT();

        if (tid < 64) {
            float mo = marr[tid];
            float mn = fmaxf(mo, fmaxf(pm0[tid], pm1[tid]));
            alpha[tid] = (mn > -1e29f) ? __expf(mo - mn) : 1.f;
            marr[tid] = mn;
        }
        __syncthreads();

        // P = exp(s - m), write hi/lo to smem, partial row sums
        {
            float mn0 = marr[rlo], mn1 = marr[rhi];
            float sum0 = 0.f, sum1 = 0.f;
#pragma unroll
            for (int n8 = 0; n8 < 4; n8++) {
                float p0 = (sacc[n8][0] > -1e29f) ? __expf(sacc[n8][0] - mn0) : 0.f;
                float p1 = (sacc[n8][1] > -1e29f) ? __expf(sacc[n8][1] - mn0) : 0.f;
                float p2 = (sacc[n8][2] > -1e29f) ? __expf(sacc[n8][2] - mn1) : 0.f;
                float p3 = (sacc[n8][3] > -1e29f) ? __expf(sacc[n8][3] - mn1) : 0.f;
                sum0 += p0 + p1; sum1 += p2 + p3;
                int cb = (Ch + n8 * 8 + (lane & 3) * 2) * 2;
                uint32_t hlo = pack2bf(p0, p1);
                uint32_t hhi = pack2bf(p2, p3);
                float r0a = __bfloat162float(__nv_bfloat16(((__nv_bfloat162*)&hlo)->x));
                float r0b = __bfloat162float(__nv_bfloat16(((__nv_bfloat162*)&hlo)->y));
                float r1a = __bfloat162float(__nv_bfloat16(((__nv_bfloat162*)&hhi)->x));
                float r1b = __bfloat162float(__nv_bfloat16(((__nv_bfloat162*)&hhi)->y));
                *(uint32_t*)(smemc + APH_OFF + rlo * 144 + cb) = hlo;
                *(uint32_t*)(smemc + APH_OFF + rhi * 144 + cb) = hhi;
                *(uint32_t*)(smemc + APL_OFF + rlo * 144 + cb) = pack2bf(p0 - r0a, p1 - r0b);
                *(uint32_t*)(smemc + APL_OFF + rhi * 144 + cb) = pack2bf(p2 - r1a, p3 - r1b);
            }
            sum0 += __shfl_xor_sync(0xffffffffu, sum0, 1);
            sum0 += __shfl_xor_sync(0xffffffffu, sum0, 2);
            sum1 += __shfl_xor_sync(0xffffffffu, sum1, 1);
            sum1 += __shfl_xor_sync(0xffffffffu, sum1, 2);
            if ((lane & 3) == 0) {
                float* psh = (w & 1) ? ps1 : ps0;
                psh[rlo] = sum0; psh[rhi] = sum1;
            }
        }
        __syncthreads();
        if (tid < 64) larr[tid] = alpha[tid] * larr[tid] + ps0[tid] + ps1[tid];
        CP_WAIT1();              // V[t] ready (next-K still pending)
        __syncthreads();

        // ---------------- PV ----------------
        {
            float a0 = alpha[Rp + rl], a1 = alpha[Rp + 8 + rl];
#pragma unroll
            for (int n8 = 0; n8 < 16; n8++) {
                oacc[n8][0] *= a0; oacc[n8][1] *= a0;
                oacc[n8][2] *= a1; oacc[n8][3] *= a1;
            }
            const int vco = ((lane >> 4) & 1) * 8;   // d sub-tile select
#pragma unroll
            for (int ks = 0; ks < 4; ks++) {
                uint32_t pH[4], pL[4];
                uint32_t pb = sb + APH_OFF + (Rp + aro) * 144 + ks * 32 + aco;
                ldsm4(pH, pb);
                ldsm4(pL, pb + (APL_OFF - APH_OFF));
#pragma unroll
                for (int dt = 0; dt < 8; dt++) {
                    uint32_t vH[4], vL[4];
                    uint32_t vb = sb + AVH_OFF +
                        (ks * 16 + (lane & 7) + 8 * ((lane >> 3) & 1)) * APITCH +
                        (Dq + dt * 16 + vco) * 2;
                    ldsm4t(vH, vb);
                    ldsm4t(vL, vb + (AVL_OFF - AVH_OFF));
                    mma16816(oacc[2 * dt], pH, vH[0], vH[1]);
                    mma16816(oacc[2 * dt], pH, vL[0], vL[1]);
                    mma16816(oacc[2 * dt], pL, vH[0], vH[1]);
                    mma16816(oacc[2 * dt + 1], pH, vH[2], vH[3]);
                    mma16816(oacc[2 * dt + 1], pH, vL[2], vL[3]);
                    mma16816(oacc[2 * dt + 1], pL, vH[2], vH[3]);
                }
            }
        }
        __syncthreads();         // V consumed; safe to overwrite next iter
    }

    // output: AO[S][HQ*HD]
    {
        float inv0 = 1.0f / larr[Rp + rl];
        float inv1 = 1.0f / larr[Rp + 8 + rl];
        const int r0 = q0 + Rp + rl;
#pragma unroll
        for (int n8 = 0; n8 < 16; n8++) {
            int col = h * HD + Dq + n8 * 8 + (lane & 3) * 2;
            *(float2*)(AO + (size_t)r0 * (HQ * HD) + col) =
                make_float2(oacc[n8][0] * inv0, oacc[n8][1] * inv0);
            *(float2*)(AO + (size_t)(r0 + 8) * (HQ * HD) + col) =
                make_float2(oacc[n8][2] * inv1, oacc[n8][3] * inv1);
        }
    }
}

// ================= launch =================
extern "C" void kernel_launch(void* const* d_in, const int* in_sizes, int n_in,
                              void* d_out, int out_size) {
    const float* hidden = (const float*)d_in[0];
    const float* cosb   = (const float*)d_in[1];
    const float* sinb   = (const float*)d_in[2];
    // d_in[3] = attention_mask (sliding window, implemented analytically)
    const float* Wq = (const float*)d_in[4];
    const float* Wk = (const float*)d_in[5];
    const float* Wv = (const float*)d_in[6];
    const float* Wo = (const float*)d_in[7];
    const float* qw = (const float*)d_in[8];
    const float* kw = (const float*)d_in[9];
    float* out = (float*)d_out;

    float *Qp, *Kp, *Vp, *AO;
    cudaGetSymbolAddress((void**)&Qp, g_Qp);
    cudaGetSymbolAddress((void**)&Kp, g_Kp);
    cudaGetSymbolAddress((void**)&Vp, g_Vp);
    cudaGetSymbolAddress((void**)&AO, g_AO);

    __nv_bfloat16 *hidh, *hidl, *wqh, *wql, *wkh, *wkl, *wvh, *wvl, *woh, *wol, *aoh, *aol;
    __nv_bfloat16 *qrh, *qrl, *krh, *krl, *vrh, *vrl;
    cudaGetSymbolAddress((void**)&hidh, g_hid_h);
    cudaGetSymbolAddress((void**)&hidl, g_hid_l);
    cudaGetSymbolAddress((void**)&wqh, g_wq_h);
    cudaGetSymbolAddress((void**)&wql, g_wq_l);
    cudaGetSymbolAddress((void**)&wkh, g_wk_h);
    cudaGetSymbolAddress((void**)&wkl, g_wk_l);
    cudaGetSymbolAddress((void**)&wvh, g_wv_h);
    cudaGetSymbolAddress((void**)&wvl, g_wv_l);
    cudaGetSymbolAddress((void**)&woh, g_wo_h);
    cudaGetSymbolAddress((void**)&wol, g_wo_l);
    cudaGetSymbolAddress((void**)&aoh, g_ao_h);
    cudaGetSymbolAddress((void**)&aol, g_ao_l);
    cudaGetSymbolAddress((void**)&qrh, g_qr_h);
    cudaGetSymbolAddress((void**)&qrl, g_qr_l);
    cudaGetSymbolAddress((void**)&krh, g_kr_h);
    cudaGetSymbolAddress((void**)&krl, g_kr_l);
    cudaGetSymbolAddress((void**)&vrh, g_vr_h);
    cudaGetSymbolAddress((void**)&vrl, g_vr_l);

    cudaFuncSetAttribute((const void*)gemm_bf16x3,
                         cudaFuncAttributeMaxDynamicSharedMemorySize, SMEM_GEMM);
    cudaFuncSetAttribute((const void*)attn_mma,
                         cudaFuncAttributeMaxDynamicSharedMemorySize, SMEM_ATTN);

    // fp32 -> bf16 hi/lo splits
    cvt_hilo<<<8192, 256>>>((const float4*)hidden, hidh, hidl, (S_LEN * H_DIM) / 4);
    cvt_hilo<<<4096, 256>>>((const float4*)Wq, wqh, wql, (HQ * HD * H_DIM) / 4);
    cvt_hilo<<<2048, 256>>>((const float4*)Wk, wkh, wkl, (HKV * HD * H_DIM) / 4);
    cvt_hilo<<<2048, 256>>>((const float4*)Wv, wvh, wvl, (HKV * HD * H_DIM) / 4);
    cvt_hilo<<<4096, 256>>>((const float4*)Wo, woh, wol, (H_DIM * HQ * HD) / 4);

    // QKV projections
    gemm_bf16x3<<<dim3(16, 32), 128, SMEM_GEMM>>>(hidh, hidl, wqh, wql, Qp, HQ * HD, H_DIM);
    gemm_bf16x3<<<dim3(8, 32), 128, SMEM_GEMM>>>(hidh, hidl, wkh, wkl, Kp, HKV * HD, H_DIM);
    gemm_bf16x3<<<dim3(8, 32), 128, SMEM_GEMM>>>(hidh, hidl, wvh, wvl, Vp, HKV * HD, H_DIM);

    // RMSNorm + RoPE -> bf16 hi/lo head-major
    norm_rope_kernel<<<dim3(S_LEN, HQ + 2 * HKV), 256>>>(
        Qp, Kp, Vp, cosb, sinb, qw, kw, qrh, qrl, krh, krl, vrh, vrl);

    // tensor-core flash attention
    attn_mma<<<dim3(S_LEN / 64, HQ), 256, SMEM_ATTN>>>(qrh, qrl, krh, krl, vrh, vrl, AO);

    // output projection
    cvt_hilo<<<8192, 256>>>((const float4*)AO, aoh, aol, (S_LEN * HQ * HD) / 4);
    gemm_bf16x3<<<dim3(16, 32), 128, SMEM_GEMM>>>(aoh, aol, woh, wol, out, H_DIM, H_DIM);
}